// round 15
// baseline (speedup 1.0000x reference)
#include <cuda_runtime.h>
#include <cstdint>

#define B_   8
#define N_   64
#define NUM_CLASSES 81
#define C_   86

typedef unsigned long long u64;

template <int LEV>
__device__ __forceinline__ void block_work(
    const float* __restrict__ boxes, const int* __restrict__ labels,
    float* __restrict__ out, int b, int lbase,
    float4* s_sb, int* s_sl, float* s_area, u64* s_cand, u64 (*s_cov)[2])
{
    constexpr int    H    = (LEV == 0) ? 128 : (LEV == 1) ? 64 : (LEV == 2) ? 32
                          : (LEV == 3) ? 16 : 8;
    constexpr int    HH   = H * H;
    constexpr int    gsh  = (LEV == 0) ? 12 : (LEV == 1) ? 10 : (LEV == 2) ? 8
                          : (LEV == 3) ? 6 : 4;
    constexpr int    logH = (LEV == 0) ? 7 : (LEV == 1) ? 6 : (LEV == 2) ? 5
                          : (LEV == 3) ? 4 : 3;
    constexpr float  ps   = 1.0f / (float)H;
    constexpr float  invps= (float)H;
    constexpr float  th0  = (LEV == 0) ? 0.0078125f : (LEV == 1) ? 0.0625f
                          : (LEV == 2) ? 0.125f : (LEV == 3) ? 0.25f : 0.5f;
    constexpr float  th1  = (LEV == 0) ? 0.0625f : (LEV == 1) ? 0.125f
                          : (LEV == 2) ? 0.25f : (LEV == 3) ? 0.5f : 1.0f;
    constexpr size_t base = (LEV == 0) ? 0ull : (LEV == 1) ? 11272192ull
                          : (LEV == 2) ? 14090240ull : (LEV == 3) ? 14794752ull
                          : 14970880ull;
    constexpr size_t cs   = (size_t)HH;
    // rows this 256-unit block touches
    constexpr int    NR   = (LEV == 0) ? 8 : (LEV == 1) ? 16 : (LEV == 2) ? 32
                          : (LEV == 3) ? 16 : 8;
    constexpr int    UNITS= 8 << gsh;           // total units in this level

    const int tid = threadIdx.x;

    // ---- stage 1: stable descending-area sort into smem (threads 0-63) ----
    float4 w0;
    int lab0 = 0;
    if (tid < N_) {
        const float* bx = boxes + ((size_t)b * N_ + tid) * 4;
        w0 = make_float4(bx[0], bx[1], bx[2], bx[3]);
        lab0 = labels[(size_t)b * N_ + tid];
        s_area[tid] = (w0.z - w0.x) * (w0.w - w0.y);
    }
    __syncthreads();
    if (tid < N_) {
        float a = s_area[tid];
        int rank = 0;
#pragma unroll
        for (int j = 0; j < N_; j++) {
            float aj = s_area[j];
            rank += (aj > a) || (aj == a && j < tid);   // stable descending
        }
        s_sb[rank] = w0;
        s_sl[rank] = lab0;
    }
    __syncthreads();

    // ---- stage 2: per-row cand/cov masks (warp per row, validated) ----
    int y0;
    if (LEV <= 1) { int g0 = lbase & ((1 << gsh) - 1); y0 = (g0 << 2) >> logH; }
    else          { y0 = 0; }

    const int wid  = tid >> 5;
    const int lane = tid & 31;
#pragma unroll
    for (int ry = wid; ry < NR; ry += 8) {
        const int   y  = y0 + ry;
        const float my = ((float)y + 0.5f) * ps;
        u64 cv0 = 0ull, cv1 = 0ull, cand = 0ull;
#pragma unroll
        for (int t = 0; t < 2; t++) {
            const int n = lane + t * 32;
            float4 w = s_sb[n];
            if (my >= w.y && my <= w.w) {
                float md = fmaxf(w.z - w.x, w.w - w.y);
                if (md > th0 * 0.999f && 0.5f * md <= th1 * 1.001f) cand |= 1ull << n;

                int xlo = (int)ceilf(w.x * invps - 0.5f);
                if (((float)(xlo - 1) + 0.5f) * ps >= w.x) xlo--;
                else if (((float)xlo + 0.5f) * ps < w.x)  xlo++;
                int xhi = (int)floorf(w.z * invps - 0.5f);
                if (((float)(xhi + 1) + 0.5f) * ps <= w.z) xhi++;
                else if (((float)xhi + 0.5f) * ps > w.z)   xhi--;
                if (xlo < 0) xlo = 0;
                if (xhi > H - 1) xhi = H - 1;
                if (xlo <= xhi) {
                    int l0 = xlo < 64 ? xlo : 64;
                    int h0 = (xhi + 1) < 64 ? (xhi + 1) : 64;
                    if (h0 > l0)
                        cv0 |= ((h0 == 64) ? ~0ull : ((1ull << h0) - 1)) & ~((1ull << l0) - 1);
                    int l1 = xlo - 64 > 0 ? xlo - 64 : 0;
                    int h1 = xhi + 1 - 64 > 0 ? xhi + 1 - 64 : 0;
                    if (h1 > l1)
                        cv1 |= ((h1 == 64) ? ~0ull : ((1ull << h1) - 1)) & ~((1ull << l1) - 1);
                }
            }
        }
#pragma unroll
        for (int off = 16; off > 0; off >>= 1) {
            cv0  |= __shfl_xor_sync(0xFFFFFFFFu, cv0,  off);
            cv1  |= __shfl_xor_sync(0xFFFFFFFFu, cv1,  off);
            cand |= __shfl_xor_sync(0xFFFFFFFFu, cand, off);
        }
        if (lane == 0) {
            s_cand[ry]   = cand;
            s_cov[ry][0] = cv0;
            s_cov[ry][1] = cv1;
        }
    }
    __syncthreads();

    // ---- stage 3: unit write (validated R13/R14 structure; metadata from smem) ----
    const int local = lbase + tid;
    if (local >= UNITS) return;                 // lev4 block half-active
    const int s = local >> gsh;                 // slice 0..7
    const int g = local & ((1 << gsh) - 1);

    const int gx4 = g << 2;
    const int y   = gx4 >> logH;
    const int x0  = gx4 & (H - 1);

    u64 cand = s_cand[y - y0];
    const u64 cov = (s == 0) ? s_cov[y - y0][x0 >> 6] : 0ull;

    float* rowp = out + base + (size_t)b * (C_ * cs) + (size_t)y * H + x0;
    float* clsp = rowp + 5 * cs;
    const float4 z = make_float4(0.0f, 0.0f, 0.0f, 0.0f);

    // phase 1: zero channels [11s, min(11s+11,86))
    float* slicep = rowp + (size_t)(11 * s) * cs;
    if (s == 7) {
#pragma unroll
        for (int i = 0; i < 9; i++)
            *reinterpret_cast<float4*>(slicep + (size_t)i * cs) = z;
    } else {
#pragma unroll
        for (int i = 0; i < 11; i++)
            *reinterpret_cast<float4*>(slicep + (size_t)i * cs) = z;
    }

    // phase 2: sparse values / patches
    const int sh = x0 & 63;
    if (cand == 0ull) {
        if (s == 0) {
#pragma unroll
            for (int k = 0; k < 4; k++)
                if (!((cov >> (sh + k)) & 1ull)) clsp[k] = 1.0f;   // background
        }
        return;
    }

    const float my = ((float)y + 0.5f) * ps;
    float mx[4];
#pragma unroll
    for (int k = 0; k < 4; k++) mx[k] = ((float)(x0 + k) + 0.5f) * ps;

    int win[4] = {-1, -1, -1, -1};
    while (cand) {
        const int n = __ffsll((long long)cand) - 1;
        cand &= cand - 1;
        float4 w = s_sb[n];
        float t   = my - w.y;
        float bo  = w.w - my;
        float tbx = fmaxf(t, bo);
#pragma unroll
        for (int k = 0; k < 4; k++) {
            float l = mx[k] - w.x, rr = w.z - mx[k];
            float mxv = fmaxf(fmaxf(l, rr), tbx);
            if (fminf(l, rr) >= 0.0f && mxv > th0 && mxv <= th1) win[k] = n;
        }
    }

    if (s == 0) {
        bool anyw = (win[0] >= 0) || (win[1] >= 0) || (win[2] >= 0) || (win[3] >= 0);
        if (anyw) {
            float rl[4], rt[4], rr_[4], rb[4], ce[4];
#pragma unroll
            for (int k = 0; k < 4; k++) {
                if (win[k] >= 0) {
                    float4 w = s_sb[win[k]];
                    float l  = mx[k] - w.x;
                    float t  = my    - w.y;
                    float rr = w.z - mx[k];
                    float bo = w.w - my;
                    rl[k] = l; rt[k] = t; rr_[k] = rr; rb[k] = bo;
                    float dx = fminf(l, rr),  Dx = fmaxf(l, rr);
                    float dy = fminf(t, bo),  Dy = fmaxf(t, bo);
                    float arg = (dx / (Dx != 0.0f ? Dx : 1.0f)) *
                                (dy / (Dy != 0.0f ? Dy : 1.0f));
                    ce[k] = (arg > 0.0f) ? sqrtf(arg) : 0.0f;
                } else {
                    rl[k] = rt[k] = rr_[k] = rb[k] = 0.0f;
                    ce[k] = 0.0f;
                }
            }
            *reinterpret_cast<float4*>(rowp + 0 * cs) = make_float4(rl[0], rl[1], rl[2], rl[3]);
            *reinterpret_cast<float4*>(rowp + 1 * cs) = make_float4(rt[0], rt[1], rt[2], rt[3]);
            *reinterpret_cast<float4*>(rowp + 2 * cs) = make_float4(rr_[0], rr_[1], rr_[2], rr_[3]);
            *reinterpret_cast<float4*>(rowp + 3 * cs) = make_float4(rb[0], rb[1], rb[2], rb[3]);
            *reinterpret_cast<float4*>(rowp + 4 * cs) = make_float4(ce[0], ce[1], ce[2], ce[3]);
        }
#pragma unroll
        for (int k = 0; k < 4; k++) {
            if (win[k] >= 0) {
                int lab = s_sl[win[k]];
                if (lab < 6) clsp[(size_t)lab * cs + k] = 1.0f;    // cls 0..5 in slice 0
            } else if (!((cov >> (sh + k)) & 1ull)) {
                clsp[k] = 1.0f;
            }
        }
    } else {
        const int lo = 11 * s - 5;                                  // cls range of slice
        const int hi = (s == 7) ? NUM_CLASSES : lo + 11;
#pragma unroll
        for (int k = 0; k < 4; k++) {
            if (win[k] >= 0) {
                int lab = s_sl[win[k]];
                if (lab >= lo && lab < hi) clsp[(size_t)lab * cs + k] = 1.0f;
            }
        }
    }
}

// ---------------- single mega-kernel, 256-thread blocks ----------------
// per batch: lev0 128 blocks, lev1 32, lev2 8, lev3 2, lev4 1  -> 171
__global__ __launch_bounds__(256)
void mega_kernel(const float* __restrict__ boxes,
                 const int* __restrict__ labels,
                 float* __restrict__ out) {
    __shared__ float4 s_sb[N_];
    __shared__ int    s_sl[N_];
    __shared__ float  s_area[N_];
    __shared__ u64    s_cand[32];
    __shared__ u64    s_cov[32][2];

    const int b   = blockIdx.y;
    const int blk = blockIdx.x;

    if (blk < 128)
        block_work<0>(boxes, labels, out, b, blk * 256,          s_sb, s_sl, s_area, s_cand, s_cov);
    else if (blk < 160)
        block_work<1>(boxes, labels, out, b, (blk - 128) * 256,  s_sb, s_sl, s_area, s_cand, s_cov);
    else if (blk < 168)
        block_work<2>(boxes, labels, out, b, (blk - 160) * 256,  s_sb, s_sl, s_area, s_cand, s_cov);
    else if (blk < 170)
        block_work<3>(boxes, labels, out, b, (blk - 168) * 256,  s_sb, s_sl, s_area, s_cand, s_cov);
    else
        block_work<4>(boxes, labels, out, b, 0,                  s_sb, s_sl, s_area, s_cand, s_cov);
}

extern "C" void kernel_launch(void* const* d_in, const int* in_sizes, int n_in,
                              void* d_out, int out_size) {
    const float* boxes  = (const float*)d_in[0];
    const int*   labels = (const int*)d_in[1];
    float* out = (float*)d_out;

    dim3 grid(171, B_);    // 1368 self-contained blocks, one launch
    mega_kernel<<<grid, 256>>>(boxes, labels, out);
}